// round 13
// baseline (speedup 1.0000x reference)
#include <cuda_runtime.h>

#define BB   8
#define CIN  32
#define COUT 32
#define HH   128
#define WW   128
#define SS   1024
#define JJ   (HH*WW)
#define NPROD 256          // producer blocks (one per (b,i))
#define NCONS 256          // consumer blocks (one per (b,o))

// Scratch: overwritten every launch. Counters are monotone (producers add 32
// per batch per launch, consumers add 32 per batch per launch) -> replay-safe
// epoch arithmetic, no resets.
__device__ float g_T[BB*CIN];
__device__ float g_U[BB*CIN];
__device__ float g_V[BB*CIN];
__device__ unsigned int g_prod[BB];   // producer arrivals per batch
__device__ unsigned int g_cons[BB];   // consumer arrivals per batch

__global__ void __launch_bounds__(256) nystrom_pc(
    const float* __restrict__ v,        // [B, CIN, H, W]
    const float* __restrict__ weight,   // [COUT, CIN, 2]
    const int*   __restrict__ idx32,    // int32 or int64 (detected)
    float*       __restrict__ out)      // [B, COUT, H, W]
{
    const int tid  = threadIdx.x;
    const int lane = tid & 31;
    const int warp = tid >> 5;
    const float step = 2.0f / 127.0f;

    if (blockIdx.x < NPROD) {
        // ================= PRODUCER: gather T/U/V for one (b,i) ==============
        const int bi = blockIdx.x;
        const int b  = bi >> 5;
        const float* plane = v + (size_t)bi * JJ;

        // indices are a permutation (distinct); three zeros at int32 positions
        // 1,3,5 can only be int64 high-halves.
        const bool is64 = (idx32[1] == 0) && (idx32[3] == 0) && (idx32[5] == 0);

        float t = 0.f, u = 0.f, w = 0.f;
        #pragma unroll
        for (int k = 0; k < 4; ++k) {
            const int s = tid + k * 256;
            const int j = is64 ? idx32[2 * s] : idx32[s];
            const float x = -1.0f + step * (float)(j & (WW - 1));
            const float y = -1.0f + step * (float)(j >> 7);
            const float val = __ldg(plane + j);
            t += val;
            u  = fmaf(x, val, u);
            w  = fmaf(y, val, w);
        }
        #pragma unroll
        for (int off = 16; off > 0; off >>= 1) {
            t += __shfl_down_sync(0xffffffffu, t, off);
            u += __shfl_down_sync(0xffffffffu, u, off);
            w += __shfl_down_sync(0xffffffffu, w, off);
        }
        __shared__ float sred[3][8];
        if (lane == 0) { sred[0][warp] = t; sred[1][warp] = u; sred[2][warp] = w; }
        __syncthreads();
        if (warp == 0) {
            float T = (lane < 8) ? sred[0][lane] : 0.f;
            float U = (lane < 8) ? sred[1][lane] : 0.f;
            float V = (lane < 8) ? sred[2][lane] : 0.f;
            #pragma unroll
            for (int off = 4; off > 0; off >>= 1) {
                T += __shfl_down_sync(0xffffffffu, T, off);
                U += __shfl_down_sync(0xffffffffu, U, off);
                V += __shfl_down_sync(0xffffffffu, V, off);
            }
            if (lane == 0) {
                g_T[bi] = T; g_U[bi] = U; g_V[bi] = V;
                __threadfence();                  // publish before arrival
                atomicAdd(&g_prod[b], 1u);        // signal
            }
        }
        return;                                   // free the SM slot
    }

    // ================= CONSUMER: fill one plane (b,o) =========================
    const int pl = blockIdx.x - NPROD;            // b*32 + o
    const int b  = pl >> 5;
    const int o  = pl & 31;

    // Independent setup BEFORE waiting (overlaps producers' gather).
    const float2 wv = ((const float2*)weight)[o * CIN + lane];
    float4* outp = (float4*)(out + (size_t)pl * JJ);

    // Wait for this batch's 32 producers (overlapped with the setup above and
    // with other blocks' execution; poll is atomic read on a per-batch word,
    // 32 consumer contenders per address).
    if (tid == 0) {
        const unsigned int old   = atomicAdd(&g_cons[b], 1u);  // my epoch ticket
        const unsigned int epoch = old >> 5;                   // old / 32
        const unsigned int need  = (epoch + 1u) * 32u;         // producer target
        while (atomicAdd(&g_prod[b], 0u) < need) { __nanosleep(64); }
        __threadfence();                                       // acquire
    }
    __syncthreads();

    // Warp-parallel dot: lane = channel. L2 loads (bypass stale L1).
    const float T = __ldcg(g_T + b * CIN + lane);
    const float U = __ldcg(g_U + b * CIN + lane);
    const float V = __ldcg(g_V + b * CIN + lane);

    float p  = T * wv.x;
    float qd = T * wv.y;
    float r  = fmaf(U, wv.x, V * wv.y);
    #pragma unroll
    for (int off = 16; off > 0; off >>= 1) {
        p  += __shfl_xor_sync(0xffffffffu, p,  off);
        qd += __shfl_xor_sync(0xffffffffu, qd, off);
        r  += __shfl_xor_sync(0xffffffffu, r,  off);
    }
    const float P = p, Q = qd, R = r;

    #pragma unroll
    for (int k = 0; k < 16; ++k) {
        const int q4 = tid + k * 256;          // float4 index in plane [0,4096)
        const int h  = q4 >> 5;
        const int wq = (q4 * 4) & (WW - 1);
        const float y = -1.0f + step * (float)h;
        const float base = fmaf(y, Q, -R);
        const float x0 = -1.0f + step * (float)wq;
        float4 o4;
        o4.x = fmaf(x0,               P, base);
        o4.y = fmaf(x0 +        step, P, base);
        o4.z = fmaf(x0 + 2.0f * step, P, base);
        o4.w = fmaf(x0 + 3.0f * step, P, base);
        outp[q4] = o4;
    }
}

extern "C" void kernel_launch(void* const* d_in, const int* in_sizes, int n_in,
                              void* d_out, int out_size)
{
    const float* v      = (const float*)d_in[0];
    const float* weight = (const float*)d_in[1];
    const int*   idx32  = (const int*)  d_in[2];
    float*       out    = (float*)d_out;

    nystrom_pc<<<NPROD + NCONS, 256>>>(v, weight, idx32, out);
}